// round 10
// baseline (speedup 1.0000x reference)
#include <cuda_runtime.h>
#include <cuda_fp16.h>
#include <cstdint>

// Problem dims (fixed by the dataset)
#define B_    32
#define NIN_  2048
#define DIN_  16
#define NOUT_ 64
#define DOUT_ 32
#define JD_   (NOUT_ * DOUT_)   // 2048

#define CHUNKS_   16            // route: i-chunks
#define ISPER_    (NIN_ / CHUNKS_)   // 128 i's per chunk
#define GROUPS_   (ISPER_ / 8)       // 16 groups of 8 i's

// Scratch (no cudaMalloc allowed -> __device__ globals)
__device__ __half g_uhat[(size_t)B_ * NIN_ * JD_];  // 268 MB, fp16 u_hat[b][i][jd]
__device__ float  g_s[B_ * JD_];                     // 256 KB, s accumulator
__device__ float  g_vsum[B_ * JD_];                  // 256 KB, sum of v across iters

// ---------------------------------------------------------------------------
// f32x2 packed-math helpers (FFMA2 — ptxas won't emit these from C++)
// ---------------------------------------------------------------------------
__device__ __forceinline__ unsigned long long pk2(float lo, float hi) {
    unsigned long long r;
    asm("mov.b64 %0, {%1,%2};" : "=l"(r) : "f"(lo), "f"(hi));
    return r;
}
__device__ __forceinline__ unsigned long long fma2(unsigned long long a,
                                                   unsigned long long b,
                                                   unsigned long long c) {
    unsigned long long d;
    asm("fma.rn.f32x2 %0, %1, %2, %3;" : "=l"(d) : "l"(a), "l"(b), "l"(c));
    return d;
}
__device__ __forceinline__ float2 upk2(unsigned long long v) {
    float2 f;
    asm("mov.b64 {%0,%1}, %2;" : "=f"(f.x), "=f"(f.y) : "l"(v));
    return f;
}

// ---------------------------------------------------------------------------
// Zero kernel: clears g_s and g_vsum once at session start
// ---------------------------------------------------------------------------
__global__ void zero_kernel() {
    int i = blockIdx.x * blockDim.x + threadIdx.x;
    if (i < B_ * JD_) {
        g_s[i] = 0.0f;
        g_vsum[i] = 0.0f;
    }
}

// ---------------------------------------------------------------------------
// K1: u_hat[b,i,jd] = sum_p x[b,i,p] * W[i,jd,p]    (store as fp16)
// One CTA per i. Thread t owns jd in [8t, 8t+8). W rows held packed as f32x2
// pairs in registers (rows 2q,2q+1 share a 64-bit reg per p) and reused across
// all 32 batches. Inner product runs on the double-width FFMA2 path.
// ---------------------------------------------------------------------------
__global__ __launch_bounds__(256, 1)
void uhat_kernel(const float* __restrict__ x, const float* __restrict__ W) {
    const int i = blockIdx.x;
    const int t = threadIdx.x;

    __shared__ float sx[B_][DIN_];   // x[:, i, :]  (2 KB)
    for (int k = t; k < B_ * DIN_; k += 256) {
        int b = k / DIN_, p = k % DIN_;
        sx[b][p] = x[((size_t)b * NIN_ + i) * DIN_ + p];
    }

    // Load 8 W rows (8 jd x 16 p); pack row pairs (2q, 2q+1) into f32x2 regs.
    unsigned long long w2[4][16];
    const float4* Wp =
        reinterpret_cast<const float4*>(W + ((size_t)i * JD_ + (size_t)t * 8) * DIN_);
#pragma unroll
    for (int q = 0; q < 4; q++) {
        float r0[16], r1[16];
#pragma unroll
        for (int c4 = 0; c4 < 4; c4++) {
            float4 a = Wp[(2 * q)     * 4 + c4];
            float4 b = Wp[(2 * q + 1) * 4 + c4];
            r0[c4 * 4 + 0] = a.x; r0[c4 * 4 + 1] = a.y;
            r0[c4 * 4 + 2] = a.z; r0[c4 * 4 + 3] = a.w;
            r1[c4 * 4 + 0] = b.x; r1[c4 * 4 + 1] = b.y;
            r1[c4 * 4 + 2] = b.z; r1[c4 * 4 + 3] = b.w;
        }
#pragma unroll
        for (int p = 0; p < 16; p++) w2[q][p] = pk2(r0[p], r1[p]);
    }
    __syncthreads();

#pragma unroll 1
    for (int b = 0; b < B_; b++) {
        unsigned long long xx[16];
#pragma unroll
        for (int p = 0; p < 16; p++) {
            float xv = sx[b][p];
            xx[p] = pk2(xv, xv);
        }

        unsigned long long acc[4];
#pragma unroll
        for (int q = 0; q < 4; q++) acc[q] = pk2(0.0f, 0.0f);

#pragma unroll
        for (int p = 0; p < 16; p++) {
#pragma unroll
            for (int q = 0; q < 4; q++) acc[q] = fma2(w2[q][p], xx[p], acc[q]);
        }

        // unpack 4 f32x2 -> 4 half2 -> one 16B store (coalesced across the warp)
        alignas(16) __half2 h[4];
#pragma unroll
        for (int q = 0; q < 4; q++) {
            float2 f = upk2(acc[q]);
            h[q] = __floats2half2_rn(f.x, f.y);
        }
        *reinterpret_cast<uint4*>(
            &g_uhat[((size_t)b * NIN_ + i) * JD_ + (size_t)t * 8]) =
            *reinterpret_cast<const uint4*>(h);
    }
}

// ---------------------------------------------------------------------------
// Routing pass: b_log = u_hat . Vsum (linearity kills the b_log state),
// softmax over j, accumulate c * u_hat into s.
// Grid: (16 i-chunks of 128, 32 batches). Thread t owns jd in [8t, 8t+8),
// j = t >> 2.  i's processed in groups of 8: 8 prefetched LDG.128 per thread
// (MLP=8), ONE barrier pair per group (32 barriers/chunk instead of 256),
// softmax for i-sub-index k handled by warp k (all 8 warps busy).
// ---------------------------------------------------------------------------
__global__ __launch_bounds__(256)
void route_kernel(int iter) {
    const int b     = blockIdx.y;
    const int chunk = blockIdx.x;
    const int t     = threadIdx.x;
    const int lane  = t & 31;
    const int wid   = t >> 5;
    const int j     = t >> 2;

    __shared__ alignas(16) float vs[JD_];      // Vsum[b,:,:]  (8 KB)
    __shared__ float blog_sm[8][NOUT_];        // 2 KB
    __shared__ float c_sm[8][NOUT_];           // 2 KB

    float vsr[8];
    if (iter > 0) {
        for (int k = t; k < JD_; k += 256) vs[k] = g_vsum[b * JD_ + k];
        __syncthreads();
        const float4* vs4 = reinterpret_cast<const float4*>(vs);
        float4 a0 = vs4[t * 2 + 0];
        float4 a1 = vs4[t * 2 + 1];
        vsr[0] = a0.x; vsr[1] = a0.y; vsr[2] = a0.z; vsr[3] = a0.w;
        vsr[4] = a1.x; vsr[5] = a1.y; vsr[6] = a1.z; vsr[7] = a1.w;
    }

    float sacc[8];
#pragma unroll
    for (int q = 0; q < 8; q++) sacc[q] = 0.0f;

    const uint4* up = reinterpret_cast<const uint4*>(
        &g_uhat[((size_t)b * NIN_ + (size_t)chunk * ISPER_) * JD_]);

    uint4 cur[8];
#pragma unroll
    for (int k = 0; k < 8; k++) cur[k] = up[k * 256 + t];   // group 0 prefetch

#pragma unroll 1
    for (int g = 0; g < GROUPS_; g++) {
        uint4 nxt[8];
        if (g < GROUPS_ - 1) {
#pragma unroll
            for (int k = 0; k < 8; k++)
                nxt[k] = up[(size_t)((g + 1) * 8 + k) * 256 + t];
        }

        if (iter > 0) {
            // b_log partials for the 8 i's of this group
#pragma unroll
            for (int k = 0; k < 8; k++) {
                const __half2* hp = reinterpret_cast<const __half2*>(&cur[k]);
                float p = 0.0f;
#pragma unroll
                for (int q = 0; q < 4; q++) {
                    float2 f = __half22float2(hp[q]);
                    p = fmaf(f.x, vsr[2 * q], p);
                    p = fmaf(f.y, vsr[2 * q + 1], p);
                }
                p += __shfl_xor_sync(0xffffffffu, p, 1);
                p += __shfl_xor_sync(0xffffffffu, p, 2);
                if ((t & 3) == 0) blog_sm[k][j] = p;
            }
            __syncthreads();

            // warp w computes softmax for i-sub-index w
            {
                float b0 = blog_sm[wid][lane];
                float b1 = blog_sm[wid][lane + 32];
                float m = fmaxf(b0, b1);
#pragma unroll
                for (int o = 16; o > 0; o >>= 1)
                    m = fmaxf(m, __shfl_xor_sync(0xffffffffu, m, o));
                float e0 = __expf(b0 - m);
                float e1 = __expf(b1 - m);
                float s = e0 + e1;
#pragma unroll
                for (int o = 16; o > 0; o >>= 1)
                    s += __shfl_xor_sync(0xffffffffu, s, o);
                float inv = 1.0f / s;
                c_sm[wid][lane]      = e0 * inv;
                c_sm[wid][lane + 32] = e1 * inv;
            }
            __syncthreads();
        }

        // accumulate c * u into register s
#pragma unroll
        for (int k = 0; k < 8; k++) {
            float c = (iter > 0) ? c_sm[k][j] : (1.0f / 64.0f);
            const __half2* hp = reinterpret_cast<const __half2*>(&cur[k]);
#pragma unroll
            for (int q = 0; q < 4; q++) {
                float2 f = __half22float2(hp[q]);
                sacc[2 * q]     = fmaf(c, f.x, sacc[2 * q]);
                sacc[2 * q + 1] = fmaf(c, f.y, sacc[2 * q + 1]);
            }
        }

#pragma unroll
        for (int k = 0; k < 8; k++) cur[k] = nxt[k];
    }

    // one atomic flush per chunk (1M lanes total across the grid)
#pragma unroll
    for (int q = 0; q < 8; q++)
        atomicAdd(&g_s[b * JD_ + t * 8 + q], sacc[q]);
}

// ---------------------------------------------------------------------------
// Squash: v = (|s|^2/(1+|s|^2)) * s/sqrt(|s|^2+eps) per (b,j) row.
// One warp per row (lane = d). Accumulates Vsum; non-final iters also reset
// g_s to zero for the next routing pass (kills 2 zero-kernel launches).
// ---------------------------------------------------------------------------
__global__ void squash_kernel(const float* __restrict__ bias,
                              float* __restrict__ out, int final_iter) {
    int idx = blockIdx.x * blockDim.x + threadIdx.x;
    if (idx >= B_ * NOUT_ * DOUT_) return;
    int d   = idx & 31;
    int row = idx >> 5;          // b*64 + j
    int j   = row & (NOUT_ - 1);

    float sval = g_s[idx] + bias[j * DOUT_ + d];
    float sq = sval * sval;
#pragma unroll
    for (int o = 16; o > 0; o >>= 1)
        sq += __shfl_xor_sync(0xffffffffu, sq, o);

    float scale = (sq / (1.0f + sq)) * rsqrtf(sq + 1e-7f);
    float v = sval * scale;

    if (final_iter) {
        out[idx] = v;
    } else {
        g_vsum[idx] += v;
        g_s[idx] = 0.0f;         // ready for the next route pass
    }
}

// ---------------------------------------------------------------------------
extern "C" void kernel_launch(void* const* d_in, const int* in_sizes, int n_in,
                              void* d_out, int out_size) {
    // Identify inputs by size (robust to metadata ordering)
    const float *x = nullptr, *W = nullptr, *bias = nullptr;
    for (int k = 0; k < n_in; k++) {
        if (in_sizes[k] == NIN_ * NOUT_ * DOUT_ * DIN_) W    = (const float*)d_in[k];
        else if (in_sizes[k] == B_ * NIN_ * DIN_)       x    = (const float*)d_in[k];
        else if (in_sizes[k] == NOUT_ * DOUT_)          bias = (const float*)d_in[k];
    }
    float* out = (float*)d_out;

    const int ZTHREADS = 256;
    const int ZBLOCKS  = (B_ * JD_ + ZTHREADS - 1) / ZTHREADS;

    zero_kernel<<<ZBLOCKS, ZTHREADS>>>();        // s = 0, vsum = 0
    uhat_kernel<<<NIN_, 256>>>(x, W);            // produce u_hat (fp16)

    for (int it = 0; it < 3; it++) {
        route_kernel<<<dim3(CHUNKS_, B_), 256>>>(it);
        squash_kernel<<<ZBLOCKS, ZTHREADS>>>(bias, out, it == 2 ? 1 : 0);
    }
}

// round 11
// speedup vs baseline: 1.0008x; 1.0008x over previous
#include <cuda_runtime.h>
#include <cuda_fp16.h>
#include <cstdint>

// Problem dims (fixed by the dataset)
#define B_    32
#define NIN_  2048
#define DIN_  16
#define NOUT_ 64
#define DOUT_ 32
#define JD_   (NOUT_ * DOUT_)   // 2048

#define CHUNKS_   16            // route: i-chunks
#define ISPER_    (NIN_ / CHUNKS_)   // 128 i's per chunk
#define GROUPS_   (ISPER_ / 8)       // 16 groups of 8 i's

// Scratch (no cudaMalloc allowed -> __device__ globals)
__device__ __half g_uhat[(size_t)B_ * NIN_ * JD_];  // 268 MB, fp16 u_hat[b][i][jd]
__device__ float  g_s[B_ * JD_];                     // 256 KB, s accumulator
__device__ float  g_vsum[B_ * JD_];                  // 256 KB, sum of v across iters

// ---------------------------------------------------------------------------
// f32x2 packed-math helpers (FFMA2 — ptxas won't emit these from C++)
// ---------------------------------------------------------------------------
__device__ __forceinline__ unsigned long long pk2(float lo, float hi) {
    unsigned long long r;
    asm("mov.b64 %0, {%1,%2};" : "=l"(r) : "f"(lo), "f"(hi));
    return r;
}
__device__ __forceinline__ unsigned long long fma2(unsigned long long a,
                                                   unsigned long long b,
                                                   unsigned long long c) {
    unsigned long long d;
    asm("fma.rn.f32x2 %0, %1, %2, %3;" : "=l"(d) : "l"(a), "l"(b), "l"(c));
    return d;
}
__device__ __forceinline__ float2 upk2(unsigned long long v) {
    float2 f;
    asm("mov.b64 {%0,%1}, %2;" : "=f"(f.x), "=f"(f.y) : "l"(v));
    return f;
}

// ---------------------------------------------------------------------------
// Zero kernel: clears g_s and g_vsum once at session start
// ---------------------------------------------------------------------------
__global__ void zero_kernel() {
    int i = blockIdx.x * blockDim.x + threadIdx.x;
    if (i < B_ * JD_) {
        g_s[i] = 0.0f;
        g_vsum[i] = 0.0f;
    }
}

// ---------------------------------------------------------------------------
// K1: u_hat[b,i,jd] = sum_p x[b,i,p] * W[i,jd,p]    (store as fp16)
// One CTA per i. Thread t owns jd in [8t, 8t+8). W rows held packed as f32x2
// pairs in registers (rows 2q,2q+1 share a 64-bit reg per p) and reused across
// all 32 batches. Inner product runs on the double-width FFMA2 path.
// ---------------------------------------------------------------------------
__global__ __launch_bounds__(256, 1)
void uhat_kernel(const float* __restrict__ x, const float* __restrict__ W) {
    const int i = blockIdx.x;
    const int t = threadIdx.x;

    __shared__ float sx[B_][DIN_];   // x[:, i, :]  (2 KB)
    for (int k = t; k < B_ * DIN_; k += 256) {
        int b = k / DIN_, p = k % DIN_;
        sx[b][p] = x[((size_t)b * NIN_ + i) * DIN_ + p];
    }

    // Load 8 W rows (8 jd x 16 p); pack row pairs (2q, 2q+1) into f32x2 regs.
    unsigned long long w2[4][16];
    const float4* Wp =
        reinterpret_cast<const float4*>(W + ((size_t)i * JD_ + (size_t)t * 8) * DIN_);
#pragma unroll
    for (int q = 0; q < 4; q++) {
        float r0[16], r1[16];
#pragma unroll
        for (int c4 = 0; c4 < 4; c4++) {
            float4 a = Wp[(2 * q)     * 4 + c4];
            float4 b = Wp[(2 * q + 1) * 4 + c4];
            r0[c4 * 4 + 0] = a.x; r0[c4 * 4 + 1] = a.y;
            r0[c4 * 4 + 2] = a.z; r0[c4 * 4 + 3] = a.w;
            r1[c4 * 4 + 0] = b.x; r1[c4 * 4 + 1] = b.y;
            r1[c4 * 4 + 2] = b.z; r1[c4 * 4 + 3] = b.w;
        }
#pragma unroll
        for (int p = 0; p < 16; p++) w2[q][p] = pk2(r0[p], r1[p]);
    }
    __syncthreads();

#pragma unroll 1
    for (int b = 0; b < B_; b++) {
        unsigned long long xx[16];
#pragma unroll
        for (int p = 0; p < 16; p++) {
            float xv = sx[b][p];
            xx[p] = pk2(xv, xv);
        }

        unsigned long long acc[4];
#pragma unroll
        for (int q = 0; q < 4; q++) acc[q] = pk2(0.0f, 0.0f);

#pragma unroll
        for (int p = 0; p < 16; p++) {
#pragma unroll
            for (int q = 0; q < 4; q++) acc[q] = fma2(w2[q][p], xx[p], acc[q]);
        }

        // unpack 4 f32x2 -> 4 half2 -> one 16B store (coalesced across the warp)
        alignas(16) __half2 h[4];
#pragma unroll
        for (int q = 0; q < 4; q++) {
            float2 f = upk2(acc[q]);
            h[q] = __floats2half2_rn(f.x, f.y);
        }
        *reinterpret_cast<uint4*>(
            &g_uhat[((size_t)b * NIN_ + i) * JD_ + (size_t)t * 8]) =
            *reinterpret_cast<const uint4*>(h);
    }
}

// ---------------------------------------------------------------------------
// Routing pass: b_log = u_hat . Vsum (linearity kills the b_log state),
// softmax over j, accumulate c * u_hat into s.
// Grid: (16 i-chunks of 128, 32 batches). Thread t owns jd in [8t, 8t+8),
// j = t >> 2.  i's processed in groups of 8: 8 prefetched LDG.128 per thread
// (MLP=8), ONE barrier pair per group (32 barriers/chunk instead of 256),
// softmax for i-sub-index k handled by warp k (all 8 warps busy).
// ---------------------------------------------------------------------------
__global__ __launch_bounds__(256)
void route_kernel(int iter) {
    const int b     = blockIdx.y;
    const int chunk = blockIdx.x;
    const int t     = threadIdx.x;
    const int lane  = t & 31;
    const int wid   = t >> 5;
    const int j     = t >> 2;

    __shared__ alignas(16) float vs[JD_];      // Vsum[b,:,:]  (8 KB)
    __shared__ float blog_sm[8][NOUT_];        // 2 KB
    __shared__ float c_sm[8][NOUT_];           // 2 KB

    float vsr[8];
    if (iter > 0) {
        for (int k = t; k < JD_; k += 256) vs[k] = g_vsum[b * JD_ + k];
        __syncthreads();
        const float4* vs4 = reinterpret_cast<const float4*>(vs);
        float4 a0 = vs4[t * 2 + 0];
        float4 a1 = vs4[t * 2 + 1];
        vsr[0] = a0.x; vsr[1] = a0.y; vsr[2] = a0.z; vsr[3] = a0.w;
        vsr[4] = a1.x; vsr[5] = a1.y; vsr[6] = a1.z; vsr[7] = a1.w;
    }

    float sacc[8];
#pragma unroll
    for (int q = 0; q < 8; q++) sacc[q] = 0.0f;

    const uint4* up = reinterpret_cast<const uint4*>(
        &g_uhat[((size_t)b * NIN_ + (size_t)chunk * ISPER_) * JD_]);

    uint4 cur[8];
#pragma unroll
    for (int k = 0; k < 8; k++) cur[k] = up[k * 256 + t];   // group 0 prefetch

#pragma unroll 1
    for (int g = 0; g < GROUPS_; g++) {
        uint4 nxt[8];
        if (g < GROUPS_ - 1) {
#pragma unroll
            for (int k = 0; k < 8; k++)
                nxt[k] = up[(size_t)((g + 1) * 8 + k) * 256 + t];
        }

        if (iter > 0) {
            // b_log partials for the 8 i's of this group
#pragma unroll
            for (int k = 0; k < 8; k++) {
                const __half2* hp = reinterpret_cast<const __half2*>(&cur[k]);
                float p = 0.0f;
#pragma unroll
                for (int q = 0; q < 4; q++) {
                    float2 f = __half22float2(hp[q]);
                    p = fmaf(f.x, vsr[2 * q], p);
                    p = fmaf(f.y, vsr[2 * q + 1], p);
                }
                p += __shfl_xor_sync(0xffffffffu, p, 1);
                p += __shfl_xor_sync(0xffffffffu, p, 2);
                if ((t & 3) == 0) blog_sm[k][j] = p;
            }
            __syncthreads();

            // warp w computes softmax for i-sub-index w
            {
                float b0 = blog_sm[wid][lane];
                float b1 = blog_sm[wid][lane + 32];
                float m = fmaxf(b0, b1);
#pragma unroll
                for (int o = 16; o > 0; o >>= 1)
                    m = fmaxf(m, __shfl_xor_sync(0xffffffffu, m, o));
                float e0 = __expf(b0 - m);
                float e1 = __expf(b1 - m);
                float s = e0 + e1;
#pragma unroll
                for (int o = 16; o > 0; o >>= 1)
                    s += __shfl_xor_sync(0xffffffffu, s, o);
                float inv = 1.0f / s;
                c_sm[wid][lane]      = e0 * inv;
                c_sm[wid][lane + 32] = e1 * inv;
            }
            __syncthreads();
        }

        // accumulate c * u into register s
#pragma unroll
        for (int k = 0; k < 8; k++) {
            float c = (iter > 0) ? c_sm[k][j] : (1.0f / 64.0f);
            const __half2* hp = reinterpret_cast<const __half2*>(&cur[k]);
#pragma unroll
            for (int q = 0; q < 4; q++) {
                float2 f = __half22float2(hp[q]);
                sacc[2 * q]     = fmaf(c, f.x, sacc[2 * q]);
                sacc[2 * q + 1] = fmaf(c, f.y, sacc[2 * q + 1]);
            }
        }

#pragma unroll
        for (int k = 0; k < 8; k++) cur[k] = nxt[k];
    }

    // one atomic flush per chunk (1M lanes total across the grid)
#pragma unroll
    for (int q = 0; q < 8; q++)
        atomicAdd(&g_s[b * JD_ + t * 8 + q], sacc[q]);
}

// ---------------------------------------------------------------------------
// Squash: v = (|s|^2/(1+|s|^2)) * s/sqrt(|s|^2+eps) per (b,j) row.
// One warp per row (lane = d). Accumulates Vsum; non-final iters also reset
// g_s to zero for the next routing pass (kills 2 zero-kernel launches).
// ---------------------------------------------------------------------------
__global__ void squash_kernel(const float* __restrict__ bias,
                              float* __restrict__ out, int final_iter) {
    int idx = blockIdx.x * blockDim.x + threadIdx.x;
    if (idx >= B_ * NOUT_ * DOUT_) return;
    int d   = idx & 31;
    int row = idx >> 5;          // b*64 + j
    int j   = row & (NOUT_ - 1);

    float sval = g_s[idx] + bias[j * DOUT_ + d];
    float sq = sval * sval;
#pragma unroll
    for (int o = 16; o > 0; o >>= 1)
        sq += __shfl_xor_sync(0xffffffffu, sq, o);

    float scale = (sq / (1.0f + sq)) * rsqrtf(sq + 1e-7f);
    float v = sval * scale;

    if (final_iter) {
        out[idx] = v;
    } else {
        g_vsum[idx] += v;
        g_s[idx] = 0.0f;         // ready for the next route pass
    }
}

// ---------------------------------------------------------------------------
extern "C" void kernel_launch(void* const* d_in, const int* in_sizes, int n_in,
                              void* d_out, int out_size) {
    // Identify inputs by size (robust to metadata ordering)
    const float *x = nullptr, *W = nullptr, *bias = nullptr;
    for (int k = 0; k < n_in; k++) {
        if (in_sizes[k] == NIN_ * NOUT_ * DOUT_ * DIN_) W    = (const float*)d_in[k];
        else if (in_sizes[k] == B_ * NIN_ * DIN_)       x    = (const float*)d_in[k];
        else if (in_sizes[k] == NOUT_ * DOUT_)          bias = (const float*)d_in[k];
    }
    float* out = (float*)d_out;

    const int ZTHREADS = 256;
    const int ZBLOCKS  = (B_ * JD_ + ZTHREADS - 1) / ZTHREADS;

    zero_kernel<<<ZBLOCKS, ZTHREADS>>>();        // s = 0, vsum = 0
    uhat_kernel<<<NIN_, 256>>>(x, W);            // produce u_hat (fp16)

    for (int it = 0; it < 3; it++) {
        route_kernel<<<dim3(CHUNKS_, B_), 256>>>(it);
        squash_kernel<<<ZBLOCKS, ZTHREADS>>>(bias, out, it == 2 ? 1 : 0);
    }
}

// round 12
// speedup vs baseline: 1.0042x; 1.0035x over previous
#include <cuda_runtime.h>
#include <cuda_fp16.h>
#include <cstdint>

// Problem dims (fixed by the dataset)
#define B_    32
#define NIN_  2048
#define DIN_  16
#define NOUT_ 64
#define DOUT_ 32
#define JD_   (NOUT_ * DOUT_)   // 2048

#define CHUNKS_   16            // route: i-chunks
#define ISPER_    (NIN_ / CHUNKS_)   // 128 i's per chunk
#define GROUPS_   (ISPER_ / 8)       // 16 groups of 8 i's

// Scratch (no cudaMalloc allowed -> __device__ globals)
__device__ __half g_uhat[(size_t)B_ * NIN_ * JD_];  // 268 MB, fp16 u_hat[b][i][jd]
__device__ float  g_s[B_ * JD_];                     // 256 KB, s accumulator
__device__ float  g_vsum[B_ * JD_];                  // 256 KB, sum of v across iters

// ---------------------------------------------------------------------------
// f32x2 packed-math helpers (FFMA2 — ptxas won't emit these from C++)
// ---------------------------------------------------------------------------
__device__ __forceinline__ unsigned long long pk2(float lo, float hi) {
    unsigned long long r;
    asm("mov.b64 %0, {%1,%2};" : "=l"(r) : "f"(lo), "f"(hi));
    return r;
}
__device__ __forceinline__ unsigned long long fma2(unsigned long long a,
                                                   unsigned long long b,
                                                   unsigned long long c) {
    unsigned long long d;
    asm("fma.rn.f32x2 %0, %1, %2, %3;" : "=l"(d) : "l"(a), "l"(b), "l"(c));
    return d;
}
__device__ __forceinline__ float2 upk2(unsigned long long v) {
    float2 f;
    asm("mov.b64 {%0,%1}, %2;" : "=f"(f.x), "=f"(f.y) : "l"(v));
    return f;
}

// ---------------------------------------------------------------------------
// Zero kernel: clears g_s and g_vsum once at session start
// ---------------------------------------------------------------------------
__global__ void zero_kernel() {
    int i = blockIdx.x * blockDim.x + threadIdx.x;
    if (i < B_ * JD_) {
        g_s[i] = 0.0f;
        g_vsum[i] = 0.0f;
    }
}

// ---------------------------------------------------------------------------
// K1: u_hat[b,i,jd] = sum_p x[b,i,p] * W[i,jd,p]    (store as fp16)
// One CTA per i. Thread t owns jd in [8t, 8t+8). W rows held packed as f32x2
// pairs in registers (rows 2q,2q+1 share a 64-bit reg per p) and reused across
// all 32 batches. Inner product runs on the double-width FFMA2 path.
// ---------------------------------------------------------------------------
__global__ __launch_bounds__(256, 1)
void uhat_kernel(const float* __restrict__ x, const float* __restrict__ W) {
    const int i = blockIdx.x;
    const int t = threadIdx.x;

    __shared__ float sx[B_][DIN_];   // x[:, i, :]  (2 KB)
    for (int k = t; k < B_ * DIN_; k += 256) {
        int b = k / DIN_, p = k % DIN_;
        sx[b][p] = x[((size_t)b * NIN_ + i) * DIN_ + p];
    }

    // Load 8 W rows (8 jd x 16 p); pack row pairs (2q, 2q+1) into f32x2 regs.
    unsigned long long w2[4][16];
    const float4* Wp =
        reinterpret_cast<const float4*>(W + ((size_t)i * JD_ + (size_t)t * 8) * DIN_);
#pragma unroll
    for (int q = 0; q < 4; q++) {
        float r0[16], r1[16];
#pragma unroll
        for (int c4 = 0; c4 < 4; c4++) {
            float4 a = Wp[(2 * q)     * 4 + c4];
            float4 b = Wp[(2 * q + 1) * 4 + c4];
            r0[c4 * 4 + 0] = a.x; r0[c4 * 4 + 1] = a.y;
            r0[c4 * 4 + 2] = a.z; r0[c4 * 4 + 3] = a.w;
            r1[c4 * 4 + 0] = b.x; r1[c4 * 4 + 1] = b.y;
            r1[c4 * 4 + 2] = b.z; r1[c4 * 4 + 3] = b.w;
        }
#pragma unroll
        for (int p = 0; p < 16; p++) w2[q][p] = pk2(r0[p], r1[p]);
    }
    __syncthreads();

#pragma unroll 1
    for (int b = 0; b < B_; b++) {
        unsigned long long xx[16];
#pragma unroll
        for (int p = 0; p < 16; p++) {
            float xv = sx[b][p];
            xx[p] = pk2(xv, xv);
        }

        unsigned long long acc[4];
#pragma unroll
        for (int q = 0; q < 4; q++) acc[q] = pk2(0.0f, 0.0f);

#pragma unroll
        for (int p = 0; p < 16; p++) {
#pragma unroll
            for (int q = 0; q < 4; q++) acc[q] = fma2(w2[q][p], xx[p], acc[q]);
        }

        // unpack 4 f32x2 -> 4 half2 -> one 16B store (coalesced across the warp)
        alignas(16) __half2 h[4];
#pragma unroll
        for (int q = 0; q < 4; q++) {
            float2 f = upk2(acc[q]);
            h[q] = __floats2half2_rn(f.x, f.y);
        }
        *reinterpret_cast<uint4*>(
            &g_uhat[((size_t)b * NIN_ + i) * JD_ + (size_t)t * 8]) =
            *reinterpret_cast<const uint4*>(h);
    }
}

// ---------------------------------------------------------------------------
// Routing pass: b_log = u_hat . Vsum (linearity kills the b_log state),
// softmax over j, accumulate c * u_hat into s.
// Grid: (16 i-chunks of 128, 32 batches). Thread t owns jd in [8t, 8t+8),
// j = t >> 2.  i's processed in groups of 8: 8 prefetched LDG.128 per thread
// (MLP=8), ONE barrier pair per group (32 barriers/chunk instead of 256),
// softmax for i-sub-index k handled by warp k (all 8 warps busy).
// ---------------------------------------------------------------------------
__global__ __launch_bounds__(256)
void route_kernel(int iter) {
    const int b     = blockIdx.y;
    const int chunk = blockIdx.x;
    const int t     = threadIdx.x;
    const int lane  = t & 31;
    const int wid   = t >> 5;
    const int j     = t >> 2;

    __shared__ alignas(16) float vs[JD_];      // Vsum[b,:,:]  (8 KB)
    __shared__ float blog_sm[8][NOUT_];        // 2 KB
    __shared__ float c_sm[8][NOUT_];           // 2 KB

    float vsr[8];
    if (iter > 0) {
        for (int k = t; k < JD_; k += 256) vs[k] = g_vsum[b * JD_ + k];
        __syncthreads();
        const float4* vs4 = reinterpret_cast<const float4*>(vs);
        float4 a0 = vs4[t * 2 + 0];
        float4 a1 = vs4[t * 2 + 1];
        vsr[0] = a0.x; vsr[1] = a0.y; vsr[2] = a0.z; vsr[3] = a0.w;
        vsr[4] = a1.x; vsr[5] = a1.y; vsr[6] = a1.z; vsr[7] = a1.w;
    }

    float sacc[8];
#pragma unroll
    for (int q = 0; q < 8; q++) sacc[q] = 0.0f;

    const uint4* up = reinterpret_cast<const uint4*>(
        &g_uhat[((size_t)b * NIN_ + (size_t)chunk * ISPER_) * JD_]);

    uint4 cur[8];
#pragma unroll
    for (int k = 0; k < 8; k++) cur[k] = up[k * 256 + t];   // group 0 prefetch

#pragma unroll 1
    for (int g = 0; g < GROUPS_; g++) {
        uint4 nxt[8];
        if (g < GROUPS_ - 1) {
#pragma unroll
            for (int k = 0; k < 8; k++)
                nxt[k] = up[(size_t)((g + 1) * 8 + k) * 256 + t];
        }

        if (iter > 0) {
            // b_log partials for the 8 i's of this group
#pragma unroll
            for (int k = 0; k < 8; k++) {
                const __half2* hp = reinterpret_cast<const __half2*>(&cur[k]);
                float p = 0.0f;
#pragma unroll
                for (int q = 0; q < 4; q++) {
                    float2 f = __half22float2(hp[q]);
                    p = fmaf(f.x, vsr[2 * q], p);
                    p = fmaf(f.y, vsr[2 * q + 1], p);
                }
                p += __shfl_xor_sync(0xffffffffu, p, 1);
                p += __shfl_xor_sync(0xffffffffu, p, 2);
                if ((t & 3) == 0) blog_sm[k][j] = p;
            }
            __syncthreads();

            // warp w computes softmax for i-sub-index w
            {
                float b0 = blog_sm[wid][lane];
                float b1 = blog_sm[wid][lane + 32];
                float m = fmaxf(b0, b1);
#pragma unroll
                for (int o = 16; o > 0; o >>= 1)
                    m = fmaxf(m, __shfl_xor_sync(0xffffffffu, m, o));
                float e0 = __expf(b0 - m);
                float e1 = __expf(b1 - m);
                float s = e0 + e1;
#pragma unroll
                for (int o = 16; o > 0; o >>= 1)
                    s += __shfl_xor_sync(0xffffffffu, s, o);
                float inv = 1.0f / s;
                c_sm[wid][lane]      = e0 * inv;
                c_sm[wid][lane + 32] = e1 * inv;
            }
            __syncthreads();
        }

        // accumulate c * u into register s
#pragma unroll
        for (int k = 0; k < 8; k++) {
            float c = (iter > 0) ? c_sm[k][j] : (1.0f / 64.0f);
            const __half2* hp = reinterpret_cast<const __half2*>(&cur[k]);
#pragma unroll
            for (int q = 0; q < 4; q++) {
                float2 f = __half22float2(hp[q]);
                sacc[2 * q]     = fmaf(c, f.x, sacc[2 * q]);
                sacc[2 * q + 1] = fmaf(c, f.y, sacc[2 * q + 1]);
            }
        }

#pragma unroll
        for (int k = 0; k < 8; k++) cur[k] = nxt[k];
    }

    // one atomic flush per chunk (1M lanes total across the grid)
#pragma unroll
    for (int q = 0; q < 8; q++)
        atomicAdd(&g_s[b * JD_ + t * 8 + q], sacc[q]);
}

// ---------------------------------------------------------------------------
// Squash: v = (|s|^2/(1+|s|^2)) * s/sqrt(|s|^2+eps) per (b,j) row.
// One warp per row (lane = d). Accumulates Vsum; non-final iters also reset
// g_s to zero for the next routing pass (kills 2 zero-kernel launches).
// ---------------------------------------------------------------------------
__global__ void squash_kernel(const float* __restrict__ bias,
                              float* __restrict__ out, int final_iter) {
    int idx = blockIdx.x * blockDim.x + threadIdx.x;
    if (idx >= B_ * NOUT_ * DOUT_) return;
    int d   = idx & 31;
    int row = idx >> 5;          // b*64 + j
    int j   = row & (NOUT_ - 1);

    float sval = g_s[idx] + bias[j * DOUT_ + d];
    float sq = sval * sval;
#pragma unroll
    for (int o = 16; o > 0; o >>= 1)
        sq += __shfl_xor_sync(0xffffffffu, sq, o);

    float scale = (sq / (1.0f + sq)) * rsqrtf(sq + 1e-7f);
    float v = sval * scale;

    if (final_iter) {
        out[idx] = v;
    } else {
        g_vsum[idx] += v;
        g_s[idx] = 0.0f;         // ready for the next route pass
    }
}

// ---------------------------------------------------------------------------
extern "C" void kernel_launch(void* const* d_in, const int* in_sizes, int n_in,
                              void* d_out, int out_size) {
    // Identify inputs by size (robust to metadata ordering)
    const float *x = nullptr, *W = nullptr, *bias = nullptr;
    for (int k = 0; k < n_in; k++) {
        if (in_sizes[k] == NIN_ * NOUT_ * DOUT_ * DIN_) W    = (const float*)d_in[k];
        else if (in_sizes[k] == B_ * NIN_ * DIN_)       x    = (const float*)d_in[k];
        else if (in_sizes[k] == NOUT_ * DOUT_)          bias = (const float*)d_in[k];
    }
    float* out = (float*)d_out;

    const int ZTHREADS = 256;
    const int ZBLOCKS  = (B_ * JD_ + ZTHREADS - 1) / ZTHREADS;

    zero_kernel<<<ZBLOCKS, ZTHREADS>>>();        // s = 0, vsum = 0
    uhat_kernel<<<NIN_, 256>>>(x, W);            // produce u_hat (fp16)

    for (int it = 0; it < 3; it++) {
        route_kernel<<<dim3(CHUNKS_, B_), 256>>>(it);
        squash_kernel<<<ZBLOCKS, ZTHREADS>>>(bias, out, it == 2 ? 1 : 0);
    }
}